// round 6
// baseline (speedup 1.0000x reference)
#include <cuda_runtime.h>

#define GH 31
#define GW 51
#define PADC 30
#define KS 61
#define NBOX 20
#define BATCH 16
#define OH 1080
#define OW 1920
#define RPB 8                 // output rows per block

// ---------------------------------------------------------------------------
// Fully fused single kernel. Every block redundantly computes the (tiny)
// separable-KDE -> conv -> grid pipeline for its batch, then streams its
// 8 output rows. No inter-block dependencies, no second launch.
//
// Separable KDE: exp(-0.5(dx^2/w + dy^2/h)) = Ex(wi)*Ey(hi), so per box only
// Ex[51], Ey[31] are needed; normalizer = (sum Ex)(sum Ey); the marginals are
//   xsal[w] = sum_n Ex_n[w]*SEy_n*inv_n + GH*bias
//   ysal[h] = sum_n Ey_n[h]*SEx_n*inv_n + GW*bias
// (Global S.sum() normalization cancels in ox/wx, oy/wy.)
// ---------------------------------------------------------------------------
__global__ __launch_bounds__(256) void fused_kernel(const float* __restrict__ bboxes,
                                                    float4* __restrict__ out) {
    const int b    = blockIdx.z;
    const int r0   = blockIdx.y * RPB;
    const int tid  = threadIdx.x;
    const int lane = tid & 31;
    const int w    = tid >> 5;

    __shared__ float exs[NBOX][GW];   // Ex_n[w] * SEy_n * inv_n
    __shared__ float eys[NBOX][GH];   // Ey_n[h] * SEx_n * inv_n
    __shared__ float xsal[GW], ysal[GH], filt[KS], xgrid[GW], ygrid[GH];
    __shared__ float yrow[RPB];

    // Gaussian filter (reference computes in float64 then casts).
    if (tid < KS) {
        double x = (double)tid - (double)PADC;
        filt[tid] = (float)exp(-4.0 * 0.693147180559945309 * x * x / (13.0 * 13.0));
    }

    // Warp w handles boxes n = w, w+8, w+16.
    for (int n = w; n < NBOX; n += 8) {
        const float* bb = bboxes + (b * NBOX + n) * 4;
        const float x1 = bb[0], y1 = bb[1], x2 = bb[2], y2 = bb[3];
        const float bw = x2 - x1, bh = y2 - y1;
        const float cx = x1 + 0.5f * bw, cy = y1 + 0.5f * bh;
        const float invw = 1.0f / bw, invh = 1.0f / bh;

        const float dx0 = cx - (float)lane * (1920.0f / 50.0f);
        const float dx1 = cx - (float)(lane + 32) * (1920.0f / 50.0f);
        const float dy0 = cy - (float)lane * (1080.0f / 30.0f);
        const float ex0 = expf(-0.5f * dx0 * dx0 * invw);
        const float ex1 = (lane < GW - 32) ? expf(-0.5f * dx1 * dx1 * invw) : 0.0f;
        const float ey0 = (lane < GH) ? expf(-0.5f * dy0 * dy0 * invh) : 0.0f;

        float sx = ex0 + ex1;
        float sy = ey0;
        #pragma unroll
        for (int s = 16; s > 0; s >>= 1) {
            sx += __shfl_xor_sync(0xffffffffu, sx, s);
            sy += __shfl_xor_sync(0xffffffffu, sy, s);
        }
        const float inv = 1.0f / (1e-5f + sx * sy);
        exs[n][lane] = ex0 * sy * inv;
        if (lane < GW - 32) exs[n][lane + 32] = ex1 * sy * inv;
        if (lane < GH)      eys[n][lane]      = ey0 * sx * inv;
    }
    __syncthreads();

    // Combine marginals (+ uniform bias summed over boxes and folded axis).
    const float bias = (float)NBOX * (1.0f / (float)(KS * KS));
    if (tid < GW) {
        float s = (float)GH * bias;
        #pragma unroll
        for (int n = 0; n < NBOX; n++) s += exs[n][tid];
        xsal[tid] = s;
    }
    if (tid >= 64 && tid < 64 + GH) {
        const int hh = tid - 64;
        float s = (float)GW * bias;
        #pragma unroll
        for (int n = 0; n < NBOX; n++) s += eys[n][hh];
        ysal[hh] = s;
    }
    __syncthreads();

    // 61-tap valid convs on reflect-padded marginals; grid = clip(o/w*2-1).
    if (tid < GW) {
        const int o = tid;
        float ws = 0.0f, os = 0.0f;
        #pragma unroll
        for (int k = 0; k < KS; k++) {
            const int j = o + k - PADC;
            const int idx = j < 0 ? -j : (j > GW - 1 ? 2 * (GW - 1) - j : j);
            const float v = xsal[idx];
            const float P = (float)(o + k - PADC) / (float)(GW - 1);
            const float f = filt[k];
            ws += v * f;
            os += P * v * f;
        }
        float g = os / ws * 2.0f - 1.0f;
        xgrid[o] = fminf(1.0f, fmaxf(-1.0f, g));
    }
    if (tid >= 64 && tid < 64 + GH) {
        const int o = tid - 64;
        float ws = 0.0f, os = 0.0f;
        #pragma unroll
        for (int k = 0; k < KS; k++) {
            const int j = o + k - PADC;
            const int idx = j < 0 ? -j : (j > GH - 1 ? 2 * (GH - 1) - j : j);
            const float v = ysal[idx];
            const float P = (float)(o + k - PADC) / (float)(GH - 1);
            const float f = filt[k];
            ws += v * f;
            os += P * v * f;
        }
        float g = os / ws * 2.0f - 1.0f;
        ygrid[o] = fminf(1.0f, fmaxf(-1.0f, g));
    }
    __syncthreads();

    // y-interp for this block's 8 rows.
    if (tid < RPB) {
        const int oy = r0 + tid;
        const float pos = (float)oy * ((float)(GH - 1) / (float)(OH - 1));
        int y0 = (int)floorf(pos);
        if (y0 > GH - 1) y0 = GH - 1;
        const float t = pos - (float)y0;
        const int y1 = min(y0 + 1, GH - 1);
        yrow[tid] = ygrid[y0] * (1.0f - t) + ygrid[y1] * t;
    }
    __syncthreads();

    // x-interp for this thread's 4 float4 slots (8 pixels).
    const int t = tid;
    float2 xv[4];
    #pragma unroll
    for (int c = 0; c < 4; c++) {
        const int q = t + c * 256;           // float4 index in row (< 960)
        if (q < OW / 2) {
            #pragma unroll
            for (int half = 0; half < 2; half++) {
                const int ox = 2 * q + half;
                const float pos = (float)ox * ((float)(GW - 1) / (float)(OW - 1));
                int x0 = (int)floorf(pos);
                if (x0 > GW - 1) x0 = GW - 1;
                const float tt = pos - (float)x0;
                const int x1 = min(x0 + 1, GW - 1);
                const float v = xgrid[x0] * (1.0f - tt) + xgrid[x1] * tt;
                if (half == 0) xv[c].x = v; else xv[c].y = v;
            }
        } else {
            xv[c] = make_float2(0.f, 0.f);
        }
    }

    float yv[RPB];
    #pragma unroll
    for (int r = 0; r < RPB; r++) yv[r] = yrow[r];

    // Streaming stores: out[b][oy][ox][{0,1}] = {x(ox), y(oy)}.
    float4* base = out + (size_t)(b * OH + r0) * (OW / 2);
    const bool has3 = (t < OW / 2 - 768);    // 960-768 = 192
    #pragma unroll
    for (int r = 0; r < RPB; r++) {
        float4* row = base + (size_t)r * (OW / 2);
        const float y = yv[r];
        __stcs(row + t,       make_float4(xv[0].x, y, xv[0].y, y));
        __stcs(row + t + 256, make_float4(xv[1].x, y, xv[1].y, y));
        __stcs(row + t + 512, make_float4(xv[2].x, y, xv[2].y, y));
        if (has3)
            __stcs(row + t + 768, make_float4(xv[3].x, y, xv[3].y, y));
    }
}

extern "C" void kernel_launch(void* const* d_in, const int* in_sizes, int n_in,
                              void* d_out, int out_size) {
    // d_in[0] = imgs (unused: only its batch dim matters, fixed at 16)
    // d_in[1] = gt_bboxes [16, 20, 4] float32
    const float* bboxes = (const float*)d_in[1];

    fused_kernel<<<dim3(1, OH / RPB, BATCH), 256>>>(bboxes, (float4*)d_out);
}

// round 7
// speedup vs baseline: 1.3725x; 1.3725x over previous
#include <cuda_runtime.h>

#define GH 31
#define GW 51
#define PADC 30
#define KS 61
#define NBOX 20
#define BATCH 16
#define OH 1080
#define OW 1920
#define RPB 8                 // output rows per fill block

// Scratch (no allocations allowed): per-batch interpolated grids.
__device__ float g_xout[BATCH * OW];
__device__ float g_yout[BATCH * OH];

// ---------------------------------------------------------------------------
// Separable KDE (R5, proven): exp(-0.5(dx^2/w+dy^2/h)) = Ex(wi)*Ey(hi).
// Per box only Ex[51], Ey[31]; normalizer = (sum Ex)(sum Ey); marginals:
//   xsal[w] = sum_n Ex_n[w]*SEy_n*inv_n + GH*bias
//   ysal[h] = sum_n Ey_n[h]*SEx_n*inv_n + GW*bias
// (Global S.sum() normalization cancels in ox/wx, oy/wy.)
// One 256-thread block per batch; warp-per-box.
// ---------------------------------------------------------------------------
__global__ __launch_bounds__(256) void sal_kernel(const float* __restrict__ bboxes) {
    const int b    = blockIdx.x;
    const int tid  = threadIdx.x;
    const int lane = tid & 31;
    const int w    = tid >> 5;

    __shared__ float exs[NBOX][GW];   // Ex_n[w] * SEy_n * inv_n
    __shared__ float eys[NBOX][GH];   // Ey_n[h] * SEx_n * inv_n
    __shared__ float xsal[GW], ysal[GH], filt[KS], xgrid[GW], ygrid[GH];

    // Gaussian filter (reference computes in float64 then casts).
    if (tid < KS) {
        double x = (double)tid - (double)PADC;
        filt[tid] = (float)exp(-4.0 * 0.693147180559945309 * x * x / (13.0 * 13.0));
    }

    // Warp w handles boxes n = w, w+8, w+16.
    for (int n = w; n < NBOX; n += 8) {
        const float* bb = bboxes + (b * NBOX + n) * 4;
        const float x1 = bb[0], y1 = bb[1], x2 = bb[2], y2 = bb[3];
        const float bw = x2 - x1, bh = y2 - y1;
        const float cx = x1 + 0.5f * bw, cy = y1 + 0.5f * bh;
        const float invw = 1.0f / bw, invh = 1.0f / bh;

        const float dx0 = cx - (float)lane * (1920.0f / 50.0f);
        const float dx1 = cx - (float)(lane + 32) * (1920.0f / 50.0f);
        const float dy0 = cy - (float)lane * (1080.0f / 30.0f);
        const float ex0 = expf(-0.5f * dx0 * dx0 * invw);
        const float ex1 = (lane < GW - 32) ? expf(-0.5f * dx1 * dx1 * invw) : 0.0f;
        const float ey0 = (lane < GH) ? expf(-0.5f * dy0 * dy0 * invh) : 0.0f;

        float sx = ex0 + ex1;
        float sy = ey0;
        #pragma unroll
        for (int s = 16; s > 0; s >>= 1) {
            sx += __shfl_xor_sync(0xffffffffu, sx, s);
            sy += __shfl_xor_sync(0xffffffffu, sy, s);
        }
        const float inv = 1.0f / (1e-5f + sx * sy);
        exs[n][lane] = ex0 * sy * inv;
        if (lane < GW - 32) exs[n][lane + 32] = ex1 * sy * inv;
        if (lane < GH)      eys[n][lane]      = ey0 * sx * inv;
    }
    __syncthreads();

    // Combine marginals (+ uniform bias summed over boxes and folded axis).
    const float bias = (float)NBOX * (1.0f / (float)(KS * KS));
    if (tid < GW) {
        float s = (float)GH * bias;
        #pragma unroll
        for (int n = 0; n < NBOX; n++) s += exs[n][tid];
        xsal[tid] = s;
    }
    if (tid >= 64 && tid < 64 + GH) {
        const int hh = tid - 64;
        float s = (float)GW * bias;
        #pragma unroll
        for (int n = 0; n < NBOX; n++) s += eys[n][hh];
        ysal[hh] = s;
    }
    __syncthreads();

    // 61-tap valid convs on reflect-padded marginals; grid = clip(o/w*2-1).
    if (tid < GW) {
        const int o = tid;
        float ws = 0.0f, os = 0.0f;
        #pragma unroll
        for (int k = 0; k < KS; k++) {
            const int j = o + k - PADC;
            const int idx = j < 0 ? -j : (j > GW - 1 ? 2 * (GW - 1) - j : j);
            const float v = xsal[idx];
            const float P = (float)(o + k - PADC) / (float)(GW - 1);
            const float f = filt[k];
            ws += v * f;
            os += P * v * f;
        }
        float g = os / ws * 2.0f - 1.0f;
        xgrid[o] = fminf(1.0f, fmaxf(-1.0f, g));
    }
    if (tid >= 64 && tid < 64 + GH) {
        const int o = tid - 64;
        float ws = 0.0f, os = 0.0f;
        #pragma unroll
        for (int k = 0; k < KS; k++) {
            const int j = o + k - PADC;
            const int idx = j < 0 ? -j : (j > GH - 1 ? 2 * (GH - 1) - j : j);
            const float v = ysal[idx];
            const float P = (float)(o + k - PADC) / (float)(GH - 1);
            const float f = filt[k];
            ws += v * f;
            os += P * v * f;
        }
        float g = os / ws * 2.0f - 1.0f;
        ygrid[o] = fminf(1.0f, fmaxf(-1.0f, g));
    }
    __syncthreads();

    // Align-corners 1D bilinear interp to the output axes.
    for (int ox = tid; ox < OW; ox += 256) {
        const float pos = (float)ox * ((float)(GW - 1) / (float)(OW - 1));
        int x0 = (int)floorf(pos);
        if (x0 > GW - 1) x0 = GW - 1;
        const float t = pos - (float)x0;
        const int x1 = min(x0 + 1, GW - 1);
        g_xout[b * OW + ox] = xgrid[x0] * (1.0f - t) + xgrid[x1] * t;
    }
    for (int oy = tid; oy < OH; oy += 256) {
        const float pos = (float)oy * ((float)(GH - 1) / (float)(OH - 1));
        int y0 = (int)floorf(pos);
        if (y0 > GH - 1) y0 = GH - 1;
        const float t = pos - (float)y0;
        const int y1 = min(y0 + 1, GH - 1);
        g_yout[b * OH + oy] = ygrid[y0] * (1.0f - t) + ygrid[y1] * t;
    }
}

// ---------------------------------------------------------------------------
// Streaming writer (R2 config: 40.3us @ 64.7% DRAM), launched with PDL.
// Blocks start during sal_kernel (launch ramp overlapped), then wait at
// cudaGridDependencySynchronize() for sal's completion (implicit trigger at
// producer grid end => full memory visibility).
// ---------------------------------------------------------------------------
__global__ __launch_bounds__(256) void fill_kernel(float4* __restrict__ out) {
    const int b  = blockIdx.z;
    const int r0 = blockIdx.y * RPB;
    const int t  = threadIdx.x;

    // Address math before the dependency sync (overlaps producer).
    const float2* xrow = reinterpret_cast<const float2*>(g_xout + b * OW);
    float4* base = out + (size_t)(b * OH + r0) * (OW / 2);
    const bool has3 = (t < OW / 2 - 768);            // 960-768 = 192

    cudaGridDependencySynchronize();

    const float2 xv0 = xrow[t];
    const float2 xv1 = xrow[t + 256];
    const float2 xv2 = xrow[t + 512];
    const float2 xv3 = has3 ? xrow[t + 768] : make_float2(0.f, 0.f);

    float yv[RPB];
    #pragma unroll
    for (int r = 0; r < RPB; r++) yv[r] = g_yout[b * OH + r0 + r];

    #pragma unroll
    for (int r = 0; r < RPB; r++) {
        float4* row = base + (size_t)r * (OW / 2);
        const float y = yv[r];
        __stcs(row + t,       make_float4(xv0.x, y, xv0.y, y));
        __stcs(row + t + 256, make_float4(xv1.x, y, xv1.y, y));
        __stcs(row + t + 512, make_float4(xv2.x, y, xv2.y, y));
        if (has3)
            __stcs(row + t + 768, make_float4(xv3.x, y, xv3.y, y));
    }
}

extern "C" void kernel_launch(void* const* d_in, const int* in_sizes, int n_in,
                              void* d_out, int out_size) {
    // d_in[0] = imgs (unused: only its batch dim matters, fixed at 16)
    // d_in[1] = gt_bboxes [16, 20, 4] float32
    const float* bboxes = (const float*)d_in[1];

    sal_kernel<<<BATCH, 256>>>(bboxes);

    // Fill with programmatic dependent launch: overlaps its launch/ramp with
    // sal_kernel; correctness guaranteed by cudaGridDependencySynchronize().
    cudaLaunchConfig_t cfg = {};
    cfg.gridDim  = dim3(1, OH / RPB, BATCH);
    cfg.blockDim = dim3(256, 1, 1);
    cfg.dynamicSmemBytes = 0;
    cfg.stream = 0;
    cudaLaunchAttribute attrs[1];
    attrs[0].id = cudaLaunchAttributeProgrammaticStreamSerialization;
    attrs[0].val.programmaticStreamSerializationAllowed = 1;
    cfg.attrs = attrs;
    cfg.numAttrs = 1;
    cudaLaunchKernelEx(&cfg, fill_kernel, (float4*)d_out);
}